// round 3
// baseline (speedup 1.0000x reference)
#include <cuda_runtime.h>
#include <cuda_bf16.h>
#include <math.h>

#define NN 100000
#define NE 1600000
#define DF 256
#define NBLK ((NN + 255) / 256)   // 391

// ---------------- scratch (static device globals; no allocation) ----------------
__device__ int   g_deg[NN];
__device__ float g_invdeg[NN];
__device__ int   g_rowptr[NN + 1];
__device__ int   g_cursor[NN];
__device__ int   g_blksum[512];
__device__ int   g_esrc[NE];
__device__ float g_neigh[(size_t)NN * DF];   // neigh1, then reused as neigh2
__device__ float g_h[(size_t)NN * DF];       // layer-1 activations

// ---------------- degree + CSR build ----------------
__global__ void k_zero_deg() {
    int i = blockIdx.x * 256 + threadIdx.x;
    if (i < NN) g_deg[i] = 0;
}

__global__ void k_hist(const int* __restrict__ dst) {
    int e = blockIdx.x * 256 + threadIdx.x;
    if (e < NE) atomicAdd(&g_deg[dst[e]], 1);
}

// per-256-block exclusive scan of deg into rowptr (local), block sums to g_blksum
__global__ void k_scanA() {
    __shared__ int sh[256];
    int b = blockIdx.x, t = threadIdx.x;
    int i = b * 256 + t;
    int v = (i < NN) ? g_deg[i] : 0;
    sh[t] = v;
    __syncthreads();
#pragma unroll
    for (int o = 1; o < 256; o <<= 1) {
        int x = (t >= o) ? sh[t - o] : 0;
        __syncthreads();
        sh[t] += x;
        __syncthreads();
    }
    if (i < NN) g_rowptr[i] = sh[t] - v;   // local exclusive
    if (t == 255) g_blksum[b] = sh[255];   // block total
}

// single-block exclusive scan of the 391 block sums
__global__ void k_scanB(int nblk) {
    __shared__ int sh[512];
    int t = threadIdx.x;
    int v = (t < nblk) ? g_blksum[t] : 0;
    sh[t] = v;
    __syncthreads();
#pragma unroll
    for (int o = 1; o < 512; o <<= 1) {
        int x = (t >= o) ? sh[t - o] : 0;
        __syncthreads();
        sh[t] += x;
        __syncthreads();
    }
    if (t < nblk) g_blksum[t] = sh[t] - v; // exclusive
}

// add block offsets -> global rowptr, init cursors, compute 1/max(deg,1)
__global__ void k_scanC() {
    int b = blockIdx.x, t = threadIdx.x;
    int i = b * 256 + t;
    if (i < NN) {
        int r = g_rowptr[i] + g_blksum[b];
        g_rowptr[i] = r;
        g_cursor[i] = r;
        int d = g_deg[i];
        g_invdeg[i] = 1.0f / (float)(d > 1 ? d : 1);
    }
    if (i == 0) g_rowptr[NN] = NE;
}

__global__ void k_scatter(const int* __restrict__ src, const int* __restrict__ dst) {
    int e = blockIdx.x * 256 + threadIdx.x;
    if (e < NE) {
        int d = dst[e];
        int p = atomicAdd(&g_cursor[d], 1);
        g_esrc[p] = src[e];
    }
}

// ---------------- mean aggregation (gather over CSR) ----------------
// block = (64,4): 4 nodes/block, 64 threads per node, float4 per thread (256 floats/row)
__device__ __forceinline__ void agg_body(const float4* __restrict__ feat,
                                         float4* __restrict__ outbuf) {
    int node = blockIdx.x * 4 + threadIdx.y;
    if (node >= NN) return;
    int t = threadIdx.x;
    int beg = g_rowptr[node];
    int end = g_rowptr[node + 1];
    float4 acc = make_float4(0.f, 0.f, 0.f, 0.f);
    int e = beg;
    for (; e + 1 < end; e += 2) {
        int s0 = g_esrc[e];
        int s1 = g_esrc[e + 1];
        float4 v0 = feat[(size_t)s0 * 64 + t];
        float4 v1 = feat[(size_t)s1 * 64 + t];
        acc.x += v0.x + v1.x;
        acc.y += v0.y + v1.y;
        acc.z += v0.z + v1.z;
        acc.w += v0.w + v1.w;
    }
    if (e < end) {
        int s0 = g_esrc[e];
        float4 v0 = feat[(size_t)s0 * 64 + t];
        acc.x += v0.x; acc.y += v0.y; acc.z += v0.z; acc.w += v0.w;
    }
    float id = g_invdeg[node];
    acc.x *= id; acc.y *= id; acc.z *= id; acc.w *= id;
    outbuf[(size_t)node * 64 + t] = acc;
}

__global__ void k_agg1(const float* __restrict__ x) {
    agg_body((const float4*)x, (float4*)g_neigh);
}

__global__ void k_agg2() {
    agg_body((const float4*)g_h, (float4*)g_neigh);
}

// ---------------- layer-1 fused GEMM + bias + sigmoid ----------------
// C[100000,256] = X@Wself + NEIGH@Wneigh + b, sigmoid -> g_h
// tiles: BM=128, BN=128, BK=8, 256 threads, 8x8 per thread, K_total=512 (concat)
__global__ __launch_bounds__(256) void k_gemm1(const float* __restrict__ X,
                                               const float* __restrict__ Ws,
                                               const float* __restrict__ Wn,
                                               const float* __restrict__ bias) {
    __shared__ float As[8][128];
    __shared__ float Bs[8][128];

    int tid  = threadIdx.x;
    int brow = blockIdx.y * 128;
    int bcol = blockIdx.x * 128;
    int ty = tid >> 4;        // 0..15
    int tx = tid & 15;        // 0..15

    int arow  = tid >> 1;         // 0..127
    int acol4 = (tid & 1) * 4;    // 0 or 4
    int bkr   = tid >> 5;         // 0..7
    int bc4   = (tid & 31) * 4;   // 0..124

    float acc[8][8];
#pragma unroll
    for (int i = 0; i < 8; i++)
#pragma unroll
        for (int j = 0; j < 8; j++) acc[i][j] = 0.f;

    for (int kt = 0; kt < 64; ++kt) {
        int k0 = kt * 8;
        const float* A = (k0 < 256) ? X : g_neigh;
        const float* B = (k0 < 256) ? Ws : Wn;
        int ka = (k0 < 256) ? k0 : (k0 - 256);

        // load A tile (128 x 8)
        int gr = brow + arow;
        float4 av = make_float4(0.f, 0.f, 0.f, 0.f);
        if (gr < NN)
            av = *(const float4*)(A + (size_t)gr * 256 + ka + acol4);
        As[acol4 + 0][arow] = av.x;
        As[acol4 + 1][arow] = av.y;
        As[acol4 + 2][arow] = av.z;
        As[acol4 + 3][arow] = av.w;

        // load B tile (8 x 128); W is [256,256] row-major, always in-bounds
        float4 bv = *(const float4*)(B + (size_t)(ka + bkr) * 256 + bcol + bc4);
        *(float4*)&Bs[bkr][bc4] = bv;

        __syncthreads();

#pragma unroll
        for (int k = 0; k < 8; ++k) {
            float a[8], bb[8];
#pragma unroll
            for (int j = 0; j < 8; j++) a[j] = As[k][ty * 8 + j];
#pragma unroll
            for (int j = 0; j < 8; j++) bb[j] = Bs[k][tx * 8 + j];
#pragma unroll
            for (int i = 0; i < 8; i++)
#pragma unroll
                for (int j = 0; j < 8; j++) acc[i][j] += a[i] * bb[j];
        }
        __syncthreads();
    }

    // epilogue: bias + sigmoid
#pragma unroll
    for (int i = 0; i < 8; i++) {
        int r = brow + ty * 8 + i;
        if (r >= NN) continue;
#pragma unroll
        for (int j = 0; j < 8; j++) {
            int c = bcol + tx * 8 + j;
            float v = acc[i][j] + bias[c];
            g_h[(size_t)r * 256 + c] = 1.0f / (1.0f + __expf(-v));
        }
    }
}

// ---------------- layer 2: two 256-dot-products per node ----------------
__global__ __launch_bounds__(256) void k_layer2(const float* __restrict__ Ws2,
                                                const float* __restrict__ Wn2,
                                                const float* __restrict__ b2,
                                                float* __restrict__ out) {
    __shared__ float ws[256], wn[256];
    int t = threadIdx.x;
    ws[t] = Ws2[t];
    wn[t] = Wn2[t];
    __syncthreads();

    int warp = t >> 5, lane = t & 31;
    int node = blockIdx.x * 8 + warp;
    if (node >= NN) return;

    const float* hr = g_h + (size_t)node * 256;
    const float* nr = g_neigh + (size_t)node * 256;
    float s = 0.f;
#pragma unroll
    for (int j = lane; j < 256; j += 32)
        s += hr[j] * ws[j] + nr[j] * wn[j];
#pragma unroll
    for (int o = 16; o > 0; o >>= 1)
        s += __shfl_down_sync(0xffffffffu, s, o);
    if (lane == 0) out[node] = s + b2[0];
}

// ---------------- launch ----------------
extern "C" void kernel_launch(void* const* d_in, const int* in_sizes, int n_in,
                              void* d_out, int out_size) {
    const float* x   = (const float*)d_in[0];
    const int*   src = (const int*)d_in[1];
    const int*   dst = (const int*)d_in[2];
    const float* Ws1 = (const float*)d_in[3];
    const float* Wn1 = (const float*)d_in[4];
    const float* b1  = (const float*)d_in[5];
    const float* Ws2 = (const float*)d_in[6];
    const float* Wn2 = (const float*)d_in[7];
    const float* b2  = (const float*)d_in[8];
    float* out = (float*)d_out;

    int edgeBlocks = (NE + 255) / 256;

    // CSR build
    k_zero_deg<<<NBLK, 256>>>();
    k_hist<<<edgeBlocks, 256>>>(dst);
    k_scanA<<<NBLK, 256>>>();
    k_scanB<<<1, 512>>>(NBLK);
    k_scanC<<<NBLK, 256>>>();
    k_scatter<<<edgeBlocks, 256>>>(src, dst);

    // layer 1
    k_agg1<<<(NN + 3) / 4, dim3(64, 4)>>>(x);
    k_gemm1<<<dim3(2, (NN + 127) / 128), 256>>>(x, Ws1, Wn1, b1);

    // layer 2
    k_agg2<<<(NN + 3) / 4, dim3(64, 4)>>>();
    k_layer2<<<(NN + 7) / 8, 256>>>(Ws2, Wn2, b2, out);
}